// round 2
// baseline (speedup 1.0000x reference)
#include <cuda_runtime.h>
#include <math.h>

#define LQ    2048
#define BQ    8
#define DQ    1024
#define NDIMQ 16
#define KDQ   (2*DQ)
#define CQ    32
#define CLQ   (LQ/CQ)       // 64
#define BD    (BQ*DQ)       // 8192

// Device scratch
__device__ float g_q [KDQ*NDIMQ];
__device__ float g_c [KDQ*NDIMQ];
__device__ float g_qp[KDQ*NDIMQ];
__device__ float g_state[2][BD*CQ*NDIMQ];
__device__ float g_carry[2][BD*CQ*NDIMQ];

__global__ __launch_bounds__(256) void coeff_kernel(
    const float* __restrict__ damp, const float* __restrict__ decay,
    const float* __restrict__ ema,  const float* __restrict__ proj)
{
    int i = blockIdx.x * blockDim.x + threadIdx.x;
    if (i >= KDQ*NDIMQ) return;
    float p  = 1.f / (1.f + expf(-damp[i]));
    float sd = 1.f / (1.f + expf(-decay[i]));
    float q  = 1.f - p * sd;
    g_q[i]  = q;
    g_c[i]  = p * ema[i] * proj[i] * 0.25f;   // 1/sqrt(16)
    g_qp[i] = powf(q, (float)CLQ);
}

// Forward chunk-local scan: writes out = sum(c1*h_local) + x*rw, stores final state
__global__ __launch_bounds__(256) void local_fwd_kernel(
    const float* __restrict__ x, const int* __restrict__ mask,
    const float* __restrict__ rw, float* __restrict__ out)
{
    int idx   = blockIdx.x * blockDim.x + threadIdx.x;   // BD*CQ
    int d     = idx & (DQ-1);
    int b     = (idx >> 10) & (BQ-1);
    int chunk = idx >> 13;
    int s     = b*DQ + d;

    float q[NDIMQ], c[NDIMQ], h[NDIMQ];
#pragma unroll
    for (int n = 0; n < NDIMQ; n++) {
        q[n] = g_q[d*NDIMQ + n];
        c[n] = g_c[d*NDIMQ + n];
        h[n] = 0.f;
    }
    float w = rw[d];
    int t0 = chunk * CLQ;

    for (int j0 = 0; j0 < CLQ; j0 += 4) {
        float xr[4], mv[4];
#pragma unroll
        for (int k = 0; k < 4; k++) {
            int t = t0 + j0 + k;
            xr[k] = x[t*BD + s];
            mv[k] = (float)mask[b*LQ + t];
        }
#pragma unroll
        for (int k = 0; k < 4; k++) {
            float xv = xr[k] * mv[k];
#pragma unroll
            for (int n = 0; n < NDIMQ; n++) h[n] = fmaf(q[n], h[n], xv);
            float a0 = 0.f, a1 = 0.f, a2 = 0.f, a3 = 0.f;
#pragma unroll
            for (int n = 0; n < NDIMQ; n += 4) {
                a0 = fmaf(c[n+0], h[n+0], a0);
                a1 = fmaf(c[n+1], h[n+1], a1);
                a2 = fmaf(c[n+2], h[n+2], a2);
                a3 = fmaf(c[n+3], h[n+3], a3);
            }
            int t = t0 + j0 + k;
            out[t*BD + s] = (a0+a1) + (a2+a3) + xr[k]*w;
        }
    }
    float* dst = &g_state[0][(s*CQ + chunk)*NDIMQ];
#pragma unroll
    for (int n = 0; n < NDIMQ; n++) dst[n] = h[n];
}

// Backward chunk-local scan: out += sum(c2*g_local), stores final state
__global__ __launch_bounds__(256) void local_bwd_kernel(
    const float* __restrict__ x, const int* __restrict__ mask,
    float* __restrict__ out)
{
    int idx   = blockIdx.x * blockDim.x + threadIdx.x;
    int d     = idx & (DQ-1);
    int b     = (idx >> 10) & (BQ-1);
    int chunk = idx >> 13;
    int s     = b*DQ + d;
    int row   = d + DQ;

    float q[NDIMQ], c[NDIMQ], g[NDIMQ];
#pragma unroll
    for (int n = 0; n < NDIMQ; n++) {
        q[n] = g_q[row*NDIMQ + n];
        c[n] = g_c[row*NDIMQ + n];
        g[n] = 0.f;
    }
    int t0 = chunk * CLQ + CLQ - 1;

    for (int j0 = 0; j0 < CLQ; j0 += 4) {
        float xr[4], mv[4];
#pragma unroll
        for (int k = 0; k < 4; k++) {
            int t = t0 - j0 - k;
            xr[k] = x[t*BD + s];
            mv[k] = (float)mask[b*LQ + t];
        }
#pragma unroll
        for (int k = 0; k < 4; k++) {
            float xv = xr[k] * mv[k];
#pragma unroll
            for (int n = 0; n < NDIMQ; n++) g[n] = fmaf(q[n], g[n], xv);
            float a0 = 0.f, a1 = 0.f, a2 = 0.f, a3 = 0.f;
#pragma unroll
            for (int n = 0; n < NDIMQ; n += 4) {
                a0 = fmaf(c[n+0], g[n+0], a0);
                a1 = fmaf(c[n+1], g[n+1], a1);
                a2 = fmaf(c[n+2], g[n+2], a2);
                a3 = fmaf(c[n+3], g[n+3], a3);
            }
            int t = t0 - j0 - k;
            out[t*BD + s] += (a0+a1) + (a2+a3);
        }
    }
    float* dst = &g_state[1][(s*CQ + chunk)*NDIMQ];
#pragma unroll
    for (int n = 0; n < NDIMQ; n++) dst[n] = g[n];
}

// Inter-chunk scan -> carry (state entering each chunk)
__global__ __launch_bounds__(256) void carry_kernel()
{
    int idx = blockIdx.x * blockDim.x + threadIdx.x;   // 2*BD*NDIMQ
    int n   = idx & (NDIMQ-1);
    int d   = (idx >> 4) & (DQ-1);
    int b   = (idx >> 14) & (BQ-1);
    int dir = idx >> 17;
    int s   = b*DQ + d;
    int row = d + dir*DQ;

    float qp = g_qp[row*NDIMQ + n];
    const float* loc = &g_state[dir][s*CQ*NDIMQ + n];
    float*       car = &g_carry[dir][s*CQ*NDIMQ + n];
    float acc = 0.f;
    if (dir == 0) {
#pragma unroll
        for (int c = 0; c < CQ; c++) {
            car[c*NDIMQ] = acc;
            acc = fmaf(qp, acc, loc[c*NDIMQ]);
        }
    } else {
#pragma unroll
        for (int c = CQ-1; c >= 0; c--) {
            car[c*NDIMQ] = acc;
            acc = fmaf(qp, acc, loc[c*NDIMQ]);
        }
    }
}

// Correction + silu: out[t] += sum_n c1*carry1*q1^{j+1}  (fwd, j asc)
//                    then v = out[t] + sum_n c2*carry2*q2^{CL-j} (bwd, j desc), silu
// Reads no x.
__global__ __launch_bounds__(256) void corr_kernel(float* __restrict__ out)
{
    int idx   = blockIdx.x * blockDim.x + threadIdx.x;   // BD*CQ
    int d     = idx & (DQ-1);
    int b     = (idx >> 10) & (BQ-1);
    int chunk = idx >> 13;
    int s     = b*DQ + d;

    // ---- forward correction ----
    {
        float q[NDIMQ], r[NDIMQ];
        const float* car = &g_carry[0][(s*CQ + chunk)*NDIMQ];
#pragma unroll
        for (int n = 0; n < NDIMQ; n++) {
            q[n] = g_q[d*NDIMQ + n];
            r[n] = g_c[d*NDIMQ + n] * car[n] * q[n];   // c*carry*q^{1}
        }
        int t0 = chunk * CLQ;
        for (int j = 0; j < CLQ; j++) {
            float a0 = 0.f, a1 = 0.f, a2 = 0.f, a3 = 0.f;
#pragma unroll
            for (int n = 0; n < NDIMQ; n += 4) {
                a0 += r[n+0]; a1 += r[n+1]; a2 += r[n+2]; a3 += r[n+3];
            }
            out[(t0 + j)*BD + s] += (a0+a1) + (a2+a3);
#pragma unroll
            for (int n = 0; n < NDIMQ; n++) r[n] *= q[n];
        }
    }
    // ---- backward correction + silu ----
    {
        float q[NDIMQ], r[NDIMQ];
        int row = d + DQ;
        const float* car = &g_carry[1][(s*CQ + chunk)*NDIMQ];
#pragma unroll
        for (int n = 0; n < NDIMQ; n++) {
            q[n] = g_q[row*NDIMQ + n];
            r[n] = g_c[row*NDIMQ + n] * car[n] * q[n];  // c*carry*q^{1} at j=CL-1
        }
        int t0 = chunk * CLQ + CLQ - 1;
        for (int j = 0; j < CLQ; j++) {
            float a0 = 0.f, a1 = 0.f, a2 = 0.f, a3 = 0.f;
#pragma unroll
            for (int n = 0; n < NDIMQ; n += 4) {
                a0 += r[n+0]; a1 += r[n+1]; a2 += r[n+2]; a3 += r[n+3];
            }
            int t = t0 - j;
            float v = out[t*BD + s] + (a0+a1) + (a2+a3);
            out[t*BD + s] = v * (1.f / (1.f + __expf(-v)));
#pragma unroll
            for (int n = 0; n < NDIMQ; n++) r[n] *= q[n];
        }
    }
}

extern "C" void kernel_launch(void* const* d_in, const int* in_sizes, int n_in,
                              void* d_out, int out_size)
{
    const float* x     = (const float*)d_in[0];
    const float* damp  = (const float*)d_in[1];
    const float* decay = (const float*)d_in[2];
    const float* ema   = (const float*)d_in[3];
    const float* proj  = (const float*)d_in[4];
    const float* rw    = (const float*)d_in[5];
    const int*   mask  = (const int*)  d_in[6];
    float* out = (float*)d_out;

    coeff_kernel<<<(KDQ*NDIMQ + 255)/256, 256>>>(damp, decay, ema, proj);
    local_fwd_kernel<<<(BD*CQ)/256, 256>>>(x, mask, rw, out);
    local_bwd_kernel<<<(BD*CQ)/256, 256>>>(x, mask, out);
    carry_kernel<<<(2*BD*NDIMQ)/256, 256>>>();
    corr_kernel<<<(BD*CQ)/256, 256>>>(out);
}

// round 3
// speedup vs baseline: 1.0607x; 1.0607x over previous
#include <cuda_runtime.h>
#include <math.h>

#define LQ    2048
#define BQ    8
#define DQ    1024
#define NDIMQ 16
#define KDQ   (2*DQ)
#define CQ    32
#define CLQ   (LQ/CQ)       // 64
#define BD    (BQ*DQ)       // 8192

// Device scratch
__device__ float g_q [KDQ*NDIMQ];
__device__ float g_c [KDQ*NDIMQ];
__device__ float g_qp[KDQ*NDIMQ];
__device__ float g_state[2][BD*CQ*NDIMQ];
__device__ float g_carry[2][BD*CQ*NDIMQ];

__global__ __launch_bounds__(256) void coeff_kernel(
    const float* __restrict__ damp, const float* __restrict__ decay,
    const float* __restrict__ ema,  const float* __restrict__ proj)
{
    int i = blockIdx.x * blockDim.x + threadIdx.x;
    if (i >= KDQ*NDIMQ) return;
    float p  = 1.f / (1.f + expf(-damp[i]));
    float sd = 1.f / (1.f + expf(-decay[i]));
    float q  = 1.f - p * sd;
    g_q[i]  = q;
    g_c[i]  = p * ema[i] * proj[i] * 0.25f;   // 1/sqrt(16)
    g_qp[i] = powf(q, (float)CLQ);
}

// ONE ascending pass over x producing BOTH chunk-local boundary states:
//   fwd final state:  h = sum_j q1^{CL-1-j} x[j]   (standard recurrence)
//   bwd final state:  g = sum_j q2^{j}      x[j]   (running-power accumulate)
__global__ __launch_bounds__(256, 2) void state_kernel(
    const float* __restrict__ x, const int* __restrict__ mask)
{
    int idx   = blockIdx.x * blockDim.x + threadIdx.x;   // BD*CQ
    int d     = idx & (DQ-1);
    int b     = (idx >> 10) & (BQ-1);
    int chunk = idx >> 13;
    int s     = b*DQ + d;

    float q1[NDIMQ], q2[NDIMQ], h[NDIMQ], g[NDIMQ], r[NDIMQ];
#pragma unroll
    for (int n = 0; n < NDIMQ; n++) {
        q1[n] = g_q[d*NDIMQ + n];
        q2[n] = g_q[(d+DQ)*NDIMQ + n];
        h[n] = 0.f; g[n] = 0.f; r[n] = 1.f;
    }
    int t0 = chunk * CLQ;

    for (int j0 = 0; j0 < CLQ; j0 += 4) {
        float xr[4], mv[4];
#pragma unroll
        for (int k = 0; k < 4; k++) {
            int t = t0 + j0 + k;
            xr[k] = x[t*BD + s];
            mv[k] = (float)mask[b*LQ + t];
        }
#pragma unroll
        for (int k = 0; k < 4; k++) {
            float xv = xr[k] * mv[k];
#pragma unroll
            for (int n = 0; n < NDIMQ; n++) {
                h[n] = fmaf(q1[n], h[n], xv);
                g[n] = fmaf(r[n], xv, g[n]);
                r[n] *= q2[n];
            }
        }
    }
    float* d0 = &g_state[0][(s*CQ + chunk)*NDIMQ];
    float* d1 = &g_state[1][(s*CQ + chunk)*NDIMQ];
#pragma unroll
    for (int n = 0; n < NDIMQ; n++) { d0[n] = h[n]; d1[n] = g[n]; }
}

// Inter-chunk scan -> carry (state entering each chunk)
__global__ __launch_bounds__(256) void carry_kernel()
{
    int idx = blockIdx.x * blockDim.x + threadIdx.x;   // 2*BD*NDIMQ
    int n   = idx & (NDIMQ-1);
    int d   = (idx >> 4) & (DQ-1);
    int b   = (idx >> 14) & (BQ-1);
    int dir = idx >> 17;
    int s   = b*DQ + d;
    int row = d + dir*DQ;

    float qp = g_qp[row*NDIMQ + n];
    const float* loc = &g_state[dir][s*CQ*NDIMQ + n];
    float*       car = &g_carry[dir][s*CQ*NDIMQ + n];
    float acc = 0.f;
    if (dir == 0) {
#pragma unroll
        for (int c = 0; c < CQ; c++) {
            car[c*NDIMQ] = acc;
            acc = fmaf(qp, acc, loc[c*NDIMQ]);
        }
    } else {
#pragma unroll
        for (int c = CQ-1; c >= 0; c--) {
            car[c*NDIMQ] = acc;
            acc = fmaf(qp, acc, loc[c*NDIMQ]);
        }
    }
}

// Final: fwd scan (carry-init) writes s1 + x*rw to out, then bwd scan
// (carry-init) re-reads x (L1-hot) + out (L2-hot), adds s2, silu, writes out.
__global__ __launch_bounds__(256, 2) void final_kernel(
    const float* __restrict__ x, const int* __restrict__ mask,
    const float* __restrict__ rw, float* __restrict__ out)
{
    int idx   = blockIdx.x * blockDim.x + threadIdx.x;   // BD*CQ
    int d     = idx & (DQ-1);
    int b     = (idx >> 10) & (BQ-1);
    int chunk = idx >> 13;
    int s     = b*DQ + d;

    // ---- forward sweep ----
    {
        float q[NDIMQ], c[NDIMQ], h[NDIMQ];
        const float* car = &g_carry[0][(s*CQ + chunk)*NDIMQ];
#pragma unroll
        for (int n = 0; n < NDIMQ; n++) {
            q[n] = g_q[d*NDIMQ + n];
            c[n] = g_c[d*NDIMQ + n];
            h[n] = car[n];
        }
        float w = rw[d];
        int t0 = chunk * CLQ;
        for (int j0 = 0; j0 < CLQ; j0 += 4) {
            float xr[4], mv[4];
#pragma unroll
            for (int k = 0; k < 4; k++) {
                int t = t0 + j0 + k;
                xr[k] = x[t*BD + s];
                mv[k] = (float)mask[b*LQ + t];
            }
#pragma unroll
            for (int k = 0; k < 4; k++) {
                float xv = xr[k] * mv[k];
#pragma unroll
                for (int n = 0; n < NDIMQ; n++) h[n] = fmaf(q[n], h[n], xv);
                float a0 = 0.f, a1 = 0.f, a2 = 0.f, a3 = 0.f;
#pragma unroll
                for (int n = 0; n < NDIMQ; n += 4) {
                    a0 = fmaf(c[n+0], h[n+0], a0);
                    a1 = fmaf(c[n+1], h[n+1], a1);
                    a2 = fmaf(c[n+2], h[n+2], a2);
                    a3 = fmaf(c[n+3], h[n+3], a3);
                }
                int t = t0 + j0 + k;
                out[t*BD + s] = (a0+a1) + (a2+a3) + xr[k]*w;
            }
        }
    }
    // ---- backward sweep + silu ----
    {
        float q[NDIMQ], c[NDIMQ], g[NDIMQ];
        int row = d + DQ;
        const float* car = &g_carry[1][(s*CQ + chunk)*NDIMQ];
#pragma unroll
        for (int n = 0; n < NDIMQ; n++) {
            q[n] = g_q[row*NDIMQ + n];
            c[n] = g_c[row*NDIMQ + n];
            g[n] = car[n];
        }
        int t0 = chunk * CLQ + CLQ - 1;
        for (int j0 = 0; j0 < CLQ; j0 += 4) {
            float xr[4], mv[4];
#pragma unroll
            for (int k = 0; k < 4; k++) {
                int t = t0 - j0 - k;
                xr[k] = x[t*BD + s];
                mv[k] = (float)mask[b*LQ + t];
            }
#pragma unroll
            for (int k = 0; k < 4; k++) {
                float xv = xr[k] * mv[k];
#pragma unroll
                for (int n = 0; n < NDIMQ; n++) g[n] = fmaf(q[n], g[n], xv);
                float a0 = 0.f, a1 = 0.f, a2 = 0.f, a3 = 0.f;
#pragma unroll
                for (int n = 0; n < NDIMQ; n += 4) {
                    a0 = fmaf(c[n+0], g[n+0], a0);
                    a1 = fmaf(c[n+1], g[n+1], a1);
                    a2 = fmaf(c[n+2], g[n+2], a2);
                    a3 = fmaf(c[n+3], g[n+3], a3);
                }
                int t = t0 - j0 - k;
                float v = out[t*BD + s] + (a0+a1) + (a2+a3);
                out[t*BD + s] = v * (1.f / (1.f + __expf(-v)));
            }
        }
    }
}

extern "C" void kernel_launch(void* const* d_in, const int* in_sizes, int n_in,
                              void* d_out, int out_size)
{
    const float* x     = (const float*)d_in[0];
    const float* damp  = (const float*)d_in[1];
    const float* decay = (const float*)d_in[2];
    const float* ema   = (const float*)d_in[3];
    const float* proj  = (const float*)d_in[4];
    const float* rw    = (const float*)d_in[5];
    const int*   mask  = (const int*)  d_in[6];
    float* out = (float*)d_out;

    coeff_kernel<<<(KDQ*NDIMQ + 255)/256, 256>>>(damp, decay, ema, proj);
    state_kernel<<<(BD*CQ)/256, 256>>>(x, mask);
    carry_kernel<<<(2*BD*NDIMQ)/256, 256>>>();
    final_kernel<<<(BD*CQ)/256, 256>>>(x, mask, rw, out);
}

// round 4
// speedup vs baseline: 1.8640x; 1.7574x over previous
#include <cuda_runtime.h>
#include <math.h>

#define LQ    2048
#define BQ    8
#define DQ    1024
#define NDIMQ 16
#define NP    8             // packed f32x2 pairs
#define KDQ   (2*DQ)
#define CQ    32
#define CLQ   (LQ/CQ)       // 64
#define BD    (BQ*DQ)       // 8192

typedef unsigned long long u64;

__device__ __forceinline__ u64 pack2(float lo, float hi) {
    u64 r; asm("mov.b64 %0,{%1,%2};" : "=l"(r) : "f"(lo), "f"(hi)); return r;
}
__device__ __forceinline__ void unpack2(u64 v, float& lo, float& hi) {
    asm("mov.b64 {%0,%1},%2;" : "=f"(lo), "=f"(hi) : "l"(v));
}
__device__ __forceinline__ u64 fma2(u64 a, u64 b, u64 c) {
    u64 d; asm("fma.rn.f32x2 %0,%1,%2,%3;" : "=l"(d) : "l"(a), "l"(b), "l"(c)); return d;
}
__device__ __forceinline__ u64 add2(u64 a, u64 b) {
    u64 d; asm("add.rn.f32x2 %0,%1,%2;" : "=l"(d) : "l"(a), "l"(b)); return d;
}

// Device scratch.  Layout of state/carry: [dir][chunk][s][n]  (carry coalesced over chunk)
__device__ float g_q [KDQ*NDIMQ];
__device__ float g_c [KDQ*NDIMQ];
__device__ float g_qp[KDQ*NDIMQ];
__device__ float g_state[2][CQ*BD*NDIMQ];
__device__ float g_carry[2][CQ*BD*NDIMQ];

__global__ __launch_bounds__(256) void coeff_kernel(
    const float* __restrict__ damp, const float* __restrict__ decay,
    const float* __restrict__ ema,  const float* __restrict__ proj)
{
    int i = blockIdx.x * blockDim.x + threadIdx.x;
    if (i >= KDQ*NDIMQ) return;
    float p  = 1.f / (1.f + expf(-damp[i]));
    float sd = 1.f / (1.f + expf(-decay[i]));
    float q  = 1.f - p * sd;
    g_q[i]  = q;
    g_c[i]  = p * ema[i] * proj[i] * 0.25f;   // 1/sqrt(16)
    g_qp[i] = powf(q, (float)CLQ);
}

// Chunk-local boundary states, both directions, two sweeps (asc h / desc g).
__global__ __launch_bounds__(256, 2) void state_kernel(
    const float* __restrict__ x, const int* __restrict__ mask)
{
    int idx   = blockIdx.x * blockDim.x + threadIdx.x;   // BD*CQ
    int d     = idx & (DQ-1);
    int b     = (idx >> 10) & (BQ-1);
    int chunk = idx >> 13;
    int s     = b*DQ + d;
    int t0    = chunk * CLQ;

    const float2* q1v = (const float2*)&g_q[d*NDIMQ];
    const float2* q2v = (const float2*)&g_q[(d+DQ)*NDIMQ];

    // ---- ascending: forward local state ----
    {
        u64 q[NP], h[NP];
#pragma unroll
        for (int p = 0; p < NP; p++) { float2 t = q1v[p]; q[p] = pack2(t.x, t.y); h[p] = 0ull; }
        for (int j0 = 0; j0 < CLQ; j0 += 4) {
            float xr[4], mv[4];
#pragma unroll
            for (int k = 0; k < 4; k++) {
                int t = t0 + j0 + k;
                xr[k] = x[t*BD + s];
                mv[k] = (float)mask[b*LQ + t];
            }
#pragma unroll
            for (int k = 0; k < 4; k++) {
                float xv = xr[k] * mv[k];
                u64 xp = pack2(xv, xv);
#pragma unroll
                for (int p = 0; p < NP; p++) h[p] = fma2(q[p], h[p], xp);
            }
        }
        u64* dst = (u64*)&g_state[0][(chunk*BD + s)*NDIMQ];
#pragma unroll
        for (int p = 0; p < NP; p++) dst[p] = h[p];
    }
    // ---- descending: backward local state ----
    {
        u64 q[NP], g[NP];
#pragma unroll
        for (int p = 0; p < NP; p++) { float2 t = q2v[p]; q[p] = pack2(t.x, t.y); g[p] = 0ull; }
        int te = t0 + CLQ - 1;
        for (int j0 = 0; j0 < CLQ; j0 += 4) {
            float xr[4], mv[4];
#pragma unroll
            for (int k = 0; k < 4; k++) {
                int t = te - j0 - k;
                xr[k] = x[t*BD + s];
                mv[k] = (float)mask[b*LQ + t];
            }
#pragma unroll
            for (int k = 0; k < 4; k++) {
                float xv = xr[k] * mv[k];
                u64 xp = pack2(xv, xv);
#pragma unroll
                for (int p = 0; p < NP; p++) g[p] = fma2(q[p], g[p], xp);
            }
        }
        u64* dst = (u64*)&g_state[1][(chunk*BD + s)*NDIMQ];
#pragma unroll
        for (int p = 0; p < NP; p++) dst[p] = g[p];
    }
}

// Inter-chunk scan -> carry (state entering each chunk). Coalesced over chunk.
__global__ __launch_bounds__(256) void carry_kernel()
{
    int idx = blockIdx.x * blockDim.x + threadIdx.x;   // 2*BD*NDIMQ
    int n   = idx & (NDIMQ-1);
    int d   = (idx >> 4) & (DQ-1);
    int b   = (idx >> 14) & (BQ-1);
    int dir = idx >> 17;
    int s   = b*DQ + d;
    int row = d + dir*DQ;
    int off = s*NDIMQ + n;

    float qp = g_qp[row*NDIMQ + n];
    const float* loc = g_state[dir];
    float*       car = g_carry[dir];
    float acc = 0.f;
    if (dir == 0) {
#pragma unroll
        for (int c = 0; c < CQ; c++) {
            car[c*(BD*NDIMQ) + off] = acc;
            acc = fmaf(qp, acc, loc[c*(BD*NDIMQ) + off]);
        }
    } else {
#pragma unroll
        for (int c = CQ-1; c >= 0; c--) {
            car[c*(BD*NDIMQ) + off] = acc;
            acc = fmaf(qp, acc, loc[c*(BD*NDIMQ) + off]);
        }
    }
}

// Final: fwd scan (carry-init) writes s1 + x*rw; bwd scan adds s2, silu.
__global__ __launch_bounds__(256, 2) void final_kernel(
    const float* __restrict__ x, const int* __restrict__ mask,
    const float* __restrict__ rw, float* __restrict__ out)
{
    int idx   = blockIdx.x * blockDim.x + threadIdx.x;   // BD*CQ
    int d     = idx & (DQ-1);
    int b     = (idx >> 10) & (BQ-1);
    int chunk = idx >> 13;
    int s     = b*DQ + d;
    int t0    = chunk * CLQ;

    // ---- forward sweep ----
    {
        u64 q[NP], c[NP], h[NP];
        const float2* qv = (const float2*)&g_q[d*NDIMQ];
        const float2* cv = (const float2*)&g_c[d*NDIMQ];
        const u64* car = (const u64*)&g_carry[0][(chunk*BD + s)*NDIMQ];
#pragma unroll
        for (int p = 0; p < NP; p++) {
            float2 tq = qv[p]; q[p] = pack2(tq.x, tq.y);
            float2 tc = cv[p]; c[p] = pack2(tc.x, tc.y);
            h[p] = car[p];
        }
        float w = rw[d];
        for (int j0 = 0; j0 < CLQ; j0 += 4) {
            float xr[4], mv[4];
#pragma unroll
            for (int k = 0; k < 4; k++) {
                int t = t0 + j0 + k;
                xr[k] = x[t*BD + s];
                mv[k] = (float)mask[b*LQ + t];
            }
#pragma unroll
            for (int k = 0; k < 4; k++) {
                float xv = xr[k] * mv[k];
                u64 xp = pack2(xv, xv);
#pragma unroll
                for (int p = 0; p < NP; p++) h[p] = fma2(q[p], h[p], xp);
                u64 a0 = fma2(c[0], h[0], 0ull);
                u64 a1 = fma2(c[1], h[1], 0ull);
                u64 a2 = fma2(c[2], h[2], 0ull);
                u64 a3 = fma2(c[3], h[3], 0ull);
                a0 = fma2(c[4], h[4], a0);
                a1 = fma2(c[5], h[5], a1);
                a2 = fma2(c[6], h[6], a2);
                a3 = fma2(c[7], h[7], a3);
                a0 = add2(a0, a1); a2 = add2(a2, a3); a0 = add2(a0, a2);
                float lo, hi; unpack2(a0, lo, hi);
                int t = t0 + j0 + k;
                out[t*BD + s] = (lo + hi) + xr[k]*w;
            }
        }
    }
    // ---- backward sweep + silu ----
    {
        u64 q[NP], c[NP], g[NP];
        int row = d + DQ;
        const float2* qv = (const float2*)&g_q[row*NDIMQ];
        const float2* cv = (const float2*)&g_c[row*NDIMQ];
        const u64* car = (const u64*)&g_carry[1][(chunk*BD + s)*NDIMQ];
#pragma unroll
        for (int p = 0; p < NP; p++) {
            float2 tq = qv[p]; q[p] = pack2(tq.x, tq.y);
            float2 tc = cv[p]; c[p] = pack2(tc.x, tc.y);
            g[p] = car[p];
        }
        int te = t0 + CLQ - 1;
        for (int j0 = 0; j0 < CLQ; j0 += 4) {
            float xr[4], mv[4];
#pragma unroll
            for (int k = 0; k < 4; k++) {
                int t = te - j0 - k;
                xr[k] = x[t*BD + s];
                mv[k] = (float)mask[b*LQ + t];
            }
#pragma unroll
            for (int k = 0; k < 4; k++) {
                float xv = xr[k] * mv[k];
                u64 xp = pack2(xv, xv);
#pragma unroll
                for (int p = 0; p < NP; p++) g[p] = fma2(q[p], g[p], xp);
                u64 a0 = fma2(c[0], g[0], 0ull);
                u64 a1 = fma2(c[1], g[1], 0ull);
                u64 a2 = fma2(c[2], g[2], 0ull);
                u64 a3 = fma2(c[3], g[3], 0ull);
                a0 = fma2(c[4], g[4], a0);
                a1 = fma2(c[5], g[5], a1);
                a2 = fma2(c[6], g[6], a2);
                a3 = fma2(c[7], g[7], a3);
                a0 = add2(a0, a1); a2 = add2(a2, a3); a0 = add2(a0, a2);
                float lo, hi; unpack2(a0, lo, hi);
                int t = te - j0 - k;
                float v = out[t*BD + s] + lo + hi;
                out[t*BD + s] = v * (1.f / (1.f + __expf(-v)));
            }
        }
    }
}

extern "C" void kernel_launch(void* const* d_in, const int* in_sizes, int n_in,
                              void* d_out, int out_size)
{
    const float* x     = (const float*)d_in[0];
    const float* damp  = (const float*)d_in[1];
    const float* decay = (const float*)d_in[2];
    const float* ema   = (const float*)d_in[3];
    const float* proj  = (const float*)d_in[4];
    const float* rw    = (const float*)d_in[5];
    const int*   mask  = (const int*)  d_in[6];
    float* out = (float*)d_out;

    coeff_kernel<<<(KDQ*NDIMQ + 255)/256, 256>>>(damp, decay, ema, proj);
    state_kernel<<<(BD*CQ)/256, 256>>>(x, mask);
    carry_kernel<<<(2*BD*NDIMQ)/256, 256>>>();
    final_kernel<<<(BD*CQ)/256, 256>>>(x, mask, rw, out);
}